// round 16
// baseline (speedup 1.0000x reference)
#include <cuda_runtime.h>
#include <cuda_bf16.h>
#include <cstdint>

#define TT 32
#define NN 20000
#define CC 10

// Scratch: U[t][n][c] = X[t,n,:]@W_ih^T + b_ih + b_hh  (fp32, 327.68 MB)
__device__ float g_U[(size_t)TT * NN * 128];

// ---------------------------------------------------------------------------
__device__ __forceinline__ uint32_t smem_u32_of(const void* p) {
    uint32_t a;
    asm("{ .reg .u64 t; cvta.to.shared.u64 t, %1; cvt.u32.u64 %0, t; }" : "=r"(a) : "l"(p));
    return a;
}
__device__ __forceinline__ void mma_bf16(float* c, const uint32_t* a, const uint32_t* b) {
    asm volatile("mma.sync.aligned.m16n8k16.row.col.f32.bf16.bf16.f32 "
        "{%0,%1,%2,%3}, {%4,%5,%6,%7}, {%8,%9}, {%0,%1,%2,%3};"
        : "+f"(c[0]), "+f"(c[1]), "+f"(c[2]), "+f"(c[3])
        : "r"(a[0]), "r"(a[1]), "r"(a[2]), "r"(a[3]), "r"(b[0]), "r"(b[1]));
}
__device__ __forceinline__ void ldsm4(uint32_t* r, uint32_t addr) {
    asm volatile("ldmatrix.sync.aligned.m8n8.x4.shared.b16 {%0,%1,%2,%3}, [%4];"
        : "=r"(r[0]), "=r"(r[1]), "=r"(r[2]), "=r"(r[3]) : "r"(addr));
}
__device__ __forceinline__ void ldsm2(uint32_t* r, uint32_t addr) {
    asm volatile("ldmatrix.sync.aligned.m8n8.x2.shared.b16 {%0,%1}, [%2];"
        : "=r"(r[0]), "=r"(r[1]) : "r"(addr));
}
// swizzled byte offset in a [rows][128] bf16 tile (256 B/row)
__device__ __forceinline__ uint32_t hswz(int r, int k) {
    int k8 = k >> 3;
    int s = (k8 & 8) | ((k8 ^ r) & 7);
    return (uint32_t)(r * 256 + s * 16 + (k & 7) * 2);
}
__device__ __forceinline__ uint32_t packbf(float a, float b) {
    uint32_t p;
    asm("cvt.rn.bf16x2.f32 %0, %1, %2;" : "=r"(p) : "f"(b), "f"(a));
    return p;
}
__device__ __forceinline__ void conv_weight(const float* __restrict__ W,
                                            char* hi, char* lo, int tid, int nthr) {
    for (int idx = tid; idx < 16384; idx += nthr) {
        int r = idx >> 7, k = idx & 127;
        float w = W[idx];
        __nv_bfloat16 wh = __float2bfloat16(w);
        uint32_t o = hswz(r, k);
        *(__nv_bfloat16*)(hi + o) = wh;
        *(__nv_bfloat16*)(lo + o) = __float2bfloat16(w - __bfloat162float(wh));
    }
}
#define CP16(dst, src) asm volatile("cp.async.cg.shared.global [%0], [%1], 16;" :: "r"(dst), "l"(src))
#define CP_COMMIT()    asm volatile("cp.async.commit_group;" ::: "memory")
#define CP_WAIT0()     asm volatile("cp.async.wait_group 0;" ::: "memory")

// ===========================================================================
// Kernel 1 (persistent, cp.async staged): U = X@Wih^T + (b_ih+b_hh).
// (byte-identical to the R14-measured ~195 us version)
// ===========================================================================
#define K1_WIH_HI 0
#define K1_WIH_LO 32768
#define K1_XBF_HI 65536     /* 32 x 256 B */
#define K1_XBF_LO 73728
#define K1_XF32   81920     /* 32 x 512 B fp32 cp.async landing */
#define K1_SMEM   98304
#define K1_TILES  20000
#define K1_GRID   296

__global__ __launch_bounds__(256, 2) void u_gemm(
    const float* __restrict__ X,
    const float* __restrict__ W_ih,
    const float* __restrict__ b_ih,
    const float* __restrict__ b_hh)
{
    extern __shared__ char sm[];
    const uint32_t sb = smem_u32_of(sm);
    const int tid = threadIdx.x, warp = tid >> 5, lane = tid & 31;
    const int g = lane >> 2, q4 = lane & 3;
    const int nw = warp * 16;
    const int cA = nw + q4 * 2;
    const int ar = lane & 15;
    const int akbase = ((lane >> 4) << 3);
    const int bn = nw + (lane & 7);
    const int bkoff = (((lane >> 3) & 1) << 3);

    auto cp_x = [&](int tl) {
#pragma unroll
        for (int j = 0; j < 4; j++) {
            int fi = tid + j * 256;               // 0..1023
            CP16(sb + K1_XF32 + fi * 16, X + (size_t)tl * 4096 + fi * 4);
        }
        CP_COMMIT();
    };

    cp_x(blockIdx.x);

    conv_weight(W_ih, sm + K1_WIH_HI, sm + K1_WIH_LO, tid, 256);
    float b4[4];
    b4[0] = b_ih[cA] + b_hh[cA];         b4[1] = b_ih[cA + 1] + b_hh[cA + 1];
    b4[2] = b_ih[cA + 8] + b_hh[cA + 8]; b4[3] = b_ih[cA + 9] + b_hh[cA + 9];

    CP_WAIT0();
    __syncthreads();

    for (int tile = blockIdx.x; tile < K1_TILES; tile += K1_GRID) {
#pragma unroll
        for (int j = 0; j < 4; j++) {
            int fi = tid + j * 256;
            int r = fi >> 5, c4 = fi & 31;
            float4 x = *(const float4*)(sm + K1_XF32 + fi * 16);
            uint32_t h0 = packbf(x.x, x.y), h1 = packbf(x.z, x.w);
            float r0 = x.x - __uint_as_float(h0 << 16);
            float r1 = x.y - __uint_as_float(h0 & 0xffff0000u);
            float r2 = x.z - __uint_as_float(h1 << 16);
            float r3 = x.w - __uint_as_float(h1 & 0xffff0000u);
            uint32_t l0 = packbf(r0, r1), l1 = packbf(r2, r3);
            *(uint2*)(sm + K1_XBF_HI + hswz(r, c4 * 4)) = make_uint2(h0, h1);
            *(uint2*)(sm + K1_XBF_LO + hswz(r, c4 * 4)) = make_uint2(l0, l1);
        }
        __syncthreads();

        if (tile + K1_GRID < K1_TILES) cp_x(tile + K1_GRID);

        float acc[2][2][4];
#pragma unroll
        for (int mt = 0; mt < 2; mt++)
#pragma unroll
            for (int nt = 0; nt < 2; nt++)
#pragma unroll
                for (int i = 0; i < 4; i++) acc[mt][nt][i] = 0.f;

#pragma unroll
        for (int k0 = 0; k0 < 8; k0++) {
            int bk = k0 * 16 + bkoff;
            uint32_t bh0[2], bh1[2], bl0[2], bl1[2];
            ldsm2(bh0, sb + K1_WIH_HI + hswz(bn, bk));
            ldsm2(bh1, sb + K1_WIH_HI + hswz(bn + 8, bk));
            ldsm2(bl0, sb + K1_WIH_LO + hswz(bn, bk));
            ldsm2(bl1, sb + K1_WIH_LO + hswz(bn + 8, bk));
            const int akb = akbase + k0 * 16;
#pragma unroll
            for (int mt = 0; mt < 2; mt++) {
                uint32_t xh[4], xl[4];
                ldsm4(xh, sb + K1_XBF_HI + hswz(mt * 16 + ar, akb));
                ldsm4(xl, sb + K1_XBF_LO + hswz(mt * 16 + ar, akb));
                mma_bf16(acc[mt][0], xh, bh0);
                mma_bf16(acc[mt][1], xh, bh1);
                mma_bf16(acc[mt][0], xh, bl0);
                mma_bf16(acc[mt][1], xh, bl1);
                mma_bf16(acc[mt][0], xl, bh0);
                mma_bf16(acc[mt][1], xl, bh1);
            }
        }

        {
            float* Ur = g_U + (size_t)tile * 4096;
#pragma unroll
            for (int mt = 0; mt < 2; mt++)
#pragma unroll
                for (int rh = 0; rh < 2; rh++) {
                    int r = mt * 16 + g + rh * 8;
                    *(float2*)(Ur + r * 128 + cA) =
                        make_float2(acc[mt][0][rh * 2] + b4[0],
                                    acc[mt][0][rh * 2 + 1] + b4[1]);
                    *(float2*)(Ur + r * 128 + cA + 8) =
                        make_float2(acc[mt][1][rh * 2] + b4[2],
                                    acc[mt][1][rh * 2 + 1] + b4[3]);
                }
        }

        CP_WAIT0();
        __syncthreads();
    }
}

// ===========================================================================
// Kernel 2 (barrier-free): 9 warps x 16 FULL rows, 288 thr, grid 139.
// Each warp owns complete rows: packs its own h tiles, quad-shfl LN, private
// softmax state, per-warp cp.async U stream. No __syncthreads in the loop.
// ===========================================================================
#define WHH_HI 0
#define WHH_LO 32768
#define H_HI   65536     /* 144 x 256 B */
#define H_LO   102400
#define UBUF   139264    /* 9 warps x 16 rows x 528 B (padded) = 76032 */
#define URSTR  528
#define UWRP   8448      /* 16 * 528 */
#define AWG_O  215296    /* float[128] = attn_W*gamma */
#define WDG_O  215808    /* float[10][128] = dense_W*gamma */
#define WGS_O  220928    /* float[10] */
#define WB_O   220968    /* float[10] */
#define SCAL_O 221008    /* float[2]: S1, S2 */
#define K2_SMEM 221056

__global__ __launch_bounds__(288, 1) void rnn_fused(
    const float* __restrict__ W_hh,
    const float* __restrict__ ln_g,  const float* __restrict__ ln_b,
    const float* __restrict__ attn_W, const float* __restrict__ attn_b,
    const float* __restrict__ dense_W, const float* __restrict__ dense_b,
    float* __restrict__ out)
{
    extern __shared__ char sm[];
    const uint32_t sb = smem_u32_of(sm);
    const int tid = threadIdx.x, warp = tid >> 5, lane = tid & 31;
    const int g = lane >> 2, q4 = lane & 3;
    const int rbase = warp * 16;               // warp's 16 rows
    const int n0 = blockIdx.x * 144;
    // A-fragment addressing (own 16 rows)
    const int ar = lane & 15;
    const int akb8 = ((lane >> 4) << 3);
    // B-fragment x4 addressing: lanes 0-7 m0(ntA,k0-7), 8-15 m1(ntA,k8-15),
    // 16-23 m2(ntB,k0-7), 24-31 m3(ntB,k8-15)
    const int b_nt_sel = (lane >> 4) & 1;
    const int b_kh = ((lane >> 3) & 1) << 3;
    const int b_row = lane & 7;

    // per-warp U stream: 16 rows x 512 B into private padded slice
    auto cpU = [&](int t) {
#pragma unroll
        for (int j = 0; j < 16; j++) {
            int fi = lane + j * 32;             // 0..511
            int rl = fi >> 5, c4 = fi & 31;
            int gr = n0 + rbase + rl; if (gr > NN - 1) gr = NN - 1;
            CP16(sb + UBUF + warp * UWRP + rl * URSTR + c4 * 16,
                 g_U + ((size_t)t * NN + gr) * 128 + c4 * 4);
        }
        CP_COMMIT();
    };
    cpU(0);

    conv_weight(W_hh, sm + WHH_HI, sm + WHH_LO, tid, 288);
    if (tid < 128) ((float*)(sm + AWG_O))[tid] = attn_W[tid] * ln_g[tid];
    for (int i = tid; i < 1280; i += 288)
        ((float*)(sm + WDG_O))[i] = dense_W[i] * ln_g[i & 127];
    if (tid >= 128 && tid < 128 + CC) {
        int c2 = tid - 128;
        float wg = 0.f, wb = 0.f;
        for (int k = 0; k < 128; k++) {
            float wd = dense_W[c2 * 128 + k];
            wg += wd * ln_g[k];
            wb += wd * ln_b[k];
        }
        ((float*)(sm + WGS_O))[c2] = wg;
        ((float*)(sm + WB_O))[c2] = wb;
    }
    if (tid == 0) {
        float s1 = 0.f, s2 = 0.f;
        for (int c = 0; c < 128; c++) {
            s1 += attn_W[c] * ln_g[c];
            s2 += attn_W[c] * ln_b[c];
        }
        ((float*)(sm + SCAL_O))[0] = s1;
        ((float*)(sm + SCAL_O))[1] = s2 + attn_b[0];
    }
    __syncthreads();   // Whh/AWG/WDG/WGS/WB/SCAL ready (only CTA-wide barrier)

    const float S1 = ((float*)(sm + SCAL_O))[0];
    const float S2 = ((float*)(sm + SCAL_O))[1];

    // ---- h0 = U[0] (biases folded in k1; no relu) ----
    CP_WAIT0();
    __syncwarp();
#pragma unroll
    for (int nt = 0; nt < 16; nt++) {
        int c = nt * 8 + q4 * 2;
#pragma unroll
        for (int rh = 0; rh < 2; rh++) {
            int rl = g + rh * 8;
            float2 u = *(float2*)(sm + UBUF + warp * UWRP + rl * URSTR + c * 4);
            uint32_t p0 = packbf(u.x, u.y);
            *(uint32_t*)(sm + H_HI + hswz(rbase + rl, c)) = p0;
            uint32_t l0 = packbf(u.x - __uint_as_float(p0 << 16),
                                 u.y - __uint_as_float(p0 & 0xffff0000u));
            *(uint32_t*)(sm + H_LO + hswz(rbase + rl, c)) = l0;
        }
    }
    __syncwarp();

    float P[16][4];
#pragma unroll
    for (int nt = 0; nt < 16; nt++)
#pragma unroll
        for (int i = 0; i < 4; i++) P[nt][i] = 0.f;
    float rs_s[2] = {0.f, 0.f}, rs_q[2] = {0.f, 0.f};
    float acc[16][4];

    // =================== time loop (no CTA barriers) ===================
    for (int t = 0; t < TT; t++) {
#pragma unroll
        for (int nt = 0; nt < 16; nt++)
#pragma unroll
            for (int i = 0; i < 4; i++) acc[nt][i] = 0.f;

        // acc = h @ Whh^T  (own rows, all 128 cols; 3 split-bf16 products)
#pragma unroll
        for (int k0 = 0; k0 < 8; k0++) {
            const int akb = k0 * 16 + akb8;
            uint32_t ah[4], al[4];
            ldsm4(ah, sb + H_HI + hswz(rbase + ar, akb));
            ldsm4(al, sb + H_LO + hswz(rbase + ar, akb));
            const int bkk = k0 * 16 + b_kh;
#pragma unroll
            for (int p = 0; p < 8; p++) {
                int brow = (2 * p + b_nt_sel) * 8 + b_row;
                uint32_t bh4[4], bl4[4];
                ldsm4(bh4, sb + WHH_HI + hswz(brow, bkk));
                ldsm4(bl4, sb + WHH_LO + hswz(brow, bkk));
                mma_bf16(acc[2 * p],     ah, &bh4[0]);
                mma_bf16(acc[2 * p + 1], ah, &bh4[2]);
                mma_bf16(acc[2 * p],     ah, &bl4[0]);
                mma_bf16(acc[2 * p + 1], ah, &bl4[2]);
                mma_bf16(acc[2 * p],     al, &bh4[0]);
                mma_bf16(acc[2 * p + 1], al, &bh4[2]);
            }
        }

        CP_WAIT0();       // U[t] landed (warp-private groups)
        __syncwarp();

        // h_{t+1} = relu(acc + U); pack own rows; LN/logit partials
        float s1[2] = {0.f, 0.f}, s2[2] = {0.f, 0.f}, lp[2] = {0.f, 0.f};
#pragma unroll
        for (int nt = 0; nt < 16; nt++) {
            int c = nt * 8 + q4 * 2;
            float2 aw = *(float2*)(sm + AWG_O + c * 4);
#pragma unroll
            for (int rh = 0; rh < 2; rh++) {
                int rl = g + rh * 8;
                float2 u = *(float2*)(sm + UBUF + warp * UWRP + rl * URSTR + c * 4);
                float v0 = fmaxf(acc[nt][rh * 2]     + u.x, 0.f);
                float v1 = fmaxf(acc[nt][rh * 2 + 1] + u.y, 0.f);
                acc[nt][rh * 2] = v0; acc[nt][rh * 2 + 1] = v1;
                uint32_t p0 = packbf(v0, v1);
                *(uint32_t*)(sm + H_HI + hswz(rbase + rl, c)) = p0;
                uint32_t l0 = packbf(v0 - __uint_as_float(p0 << 16),
                                     v1 - __uint_as_float(p0 & 0xffff0000u));
                *(uint32_t*)(sm + H_LO + hswz(rbase + rl, c)) = l0;
                s1[rh] += v0 + v1;
                s2[rh] = fmaf(v0, v0, fmaf(v1, v1, s2[rh]));
                lp[rh] = fmaf(v0, aw.x, fmaf(v1, aw.y, lp[rh]));
            }
        }
        __syncwarp();     // h tiles + U reads complete warp-wide

        // quad all-reduce + per-row finalize (max-free; logits bounded)
        float wv[2];
#pragma unroll
        for (int rh = 0; rh < 2; rh++) {
            float a = s1[rh], b = s2[rh], l = lp[rh];
            a += __shfl_xor_sync(0xffffffffu, a, 1);
            a += __shfl_xor_sync(0xffffffffu, a, 2);
            b += __shfl_xor_sync(0xffffffffu, b, 1);
            b += __shfl_xor_sync(0xffffffffu, b, 2);
            l += __shfl_xor_sync(0xffffffffu, l, 1);
            l += __shfl_xor_sync(0xffffffffu, l, 2);
            float mu = a * (1.0f / 128.0f);
            float var = fmaf(b, 1.0f / 128.0f, -mu * mu);
            float rstd = rsqrtf(var + 1e-5f);
            float ll = fmaf(rstd, l - mu * S1, S2);
            float e = __expf(ll);
            rs_s[rh] += e;
            wv[rh] = e * rstd;
            rs_q[rh] = fmaf(wv[rh], mu, rs_q[rh]);
        }

        // P += w * h  (acc holds h)
#pragma unroll
        for (int nt = 0; nt < 16; nt++)
#pragma unroll
            for (int rh = 0; rh < 2; rh++) {
                P[nt][rh * 2]     = fmaf(wv[rh], acc[nt][rh * 2],     P[nt][rh * 2]);
                P[nt][rh * 2 + 1] = fmaf(wv[rh], acc[nt][rh * 2 + 1], P[nt][rh * 2 + 1]);
            }

        if (t < TT - 1) cpU(t + 1);   // refill own U slice (warp-private)
    }

    // ---- final: out = (Σ WDG·P − q·WGS)/s + WB + dense_b  (row-local) ----
#pragma unroll
    for (int rh = 0; rh < 2; rh++) {
        int r = rbase + g + rh * 8;
        int n = n0 + r;
        float inv = 1.0f / rs_s[rh];
#pragma unroll
        for (int c2 = 0; c2 < CC; c2++) {
            float s = 0.f;
#pragma unroll
            for (int nt = 0; nt < 16; nt++) {
                int c = nt * 8 + q4 * 2;
                float2 wd = *(float2*)(sm + WDG_O + (c2 * 128 + c) * 4);
                s = fmaf(P[nt][rh * 2], wd.x, fmaf(P[nt][rh * 2 + 1], wd.y, s));
            }
            s += __shfl_xor_sync(0xffffffffu, s, 1);
            s += __shfl_xor_sync(0xffffffffu, s, 2);
            if (q4 == 0 && n < NN) {
                out[n * CC + c2] = (s - rs_q[rh] * ((float*)(sm + WGS_O))[c2]) * inv
                                   + ((float*)(sm + WB_O))[c2] + dense_b[c2];
            }
        }
    }
}

// ===========================================================================
extern "C" void kernel_launch(void* const* d_in, const int* in_sizes, int n_in,
                              void* d_out, int out_size)
{
    const float* X       = (const float*)d_in[0];
    const float* W_ih    = (const float*)d_in[1];
    const float* W_hh    = (const float*)d_in[2];
    const float* b_ih    = (const float*)d_in[3];
    const float* b_hh    = (const float*)d_in[4];
    const float* ln_g    = (const float*)d_in[5];
    const float* ln_b    = (const float*)d_in[6];
    const float* attn_W  = (const float*)d_in[7];
    const float* attn_b  = (const float*)d_in[8];
    const float* dense_W = (const float*)d_in[9];
    const float* dense_b = (const float*)d_in[10];
    float* out = (float*)d_out;

    cudaFuncSetAttribute(u_gemm, cudaFuncAttributeMaxDynamicSharedMemorySize, K1_SMEM);
    cudaFuncSetAttribute(rnn_fused, cudaFuncAttributeMaxDynamicSharedMemorySize, K2_SMEM);

    u_gemm<<<K1_GRID, 256, K1_SMEM>>>(X, W_ih, b_ih, b_hh);
    rnn_fused<<<(NN + 143) / 144, 288, K2_SMEM>>>(W_hh, ln_g, ln_b, attn_W, attn_b,
                                                  dense_W, dense_b, out);
}